// round 3
// baseline (speedup 1.0000x reference)
#include <cuda_runtime.h>

#define NN    50000
#define KCH   256
#define HEADS 8
#define OUTC  32
#define NE    800000

// ---------------- scratch (static __device__, no allocation) ----------------
__device__ float g_xp[(size_t)NN * KCH];   // projected features [N, 256]
__device__ float g_al[NN * HEADS];         // per-node left logits
__device__ float g_ar[NN * HEADS];         // per-node right logits
__device__ int   g_deg[NN];
__device__ int   g_rowptr[NN + 1];
__device__ int   g_cursor[NN];
__device__ int   g_csrsrc[NE];
__device__ int   g_is64;                   // 1 if edge_index is int64, 0 if int32

// ---------------- Kd: detect edge_index dtype (int64 vs int32) -------------
// If the buffer really holds int64 indices, every word is in [0, NN).
// If it holds int32 indices, word i = v[2i] | (v[2i+1] << 32), which is only
// < NN when v[2i+1] == 0 (prob ~2e-5 per word) -> 64 words make detection
// certain. Deterministic: same input -> same flag.
__global__ void kd_detect(const void* __restrict__ ei) {
    if (threadIdx.x != 0 || blockIdx.x != 0) return;
    const long long* p = (const long long*)ei;
    int is64 = 1;
    for (int i = 0; i < 64; i++) {
        long long v = p[i];
        if (v < 0 || v >= NN) { is64 = 0; break; }
    }
    g_is64 = is64;
}

__device__ __forceinline__ int ld_idx(const void* ei, int pos, int is64) {
    if (is64) return (int)((const long long*)ei)[pos];
    return ((const int*)ei)[pos];
}

// ---------------- K0: zero degree counters ----------------
__global__ void k0_zero() {
    int i = blockIdx.x * blockDim.x + threadIdx.x;
    if (i < NN) g_deg[i] = 0;
}

// ---------------- K1: GEMM xp = x @ W^T  (C[m,j] = sum_k A[m,k]*W[j,k]) ----
#define BM 128
#define BN 128
#define BK 16

__global__ __launch_bounds__(256) void k1_gemm(const float* __restrict__ A,
                                               const float* __restrict__ W) {
    __shared__ float As[BK][BM + 4];
    __shared__ float Bs[BK][BN + 4];

    int tid = threadIdx.x;
    int m0 = blockIdx.y * BM;
    int j0 = blockIdx.x * BN;
    int tx = tid & 15;        // 0..15 -> 8 output cols each
    int ty = tid >> 4;        // 0..15 -> 8 output rows each

    float acc[8][8];
#pragma unroll
    for (int i = 0; i < 8; i++)
#pragma unroll
        for (int j = 0; j < 8; j++) acc[i][j] = 0.f;

    int r  = tid >> 2;        // 0..63
    int kk = (tid & 3) * 4;   // 0,4,8,12

    for (int k0 = 0; k0 < KCH; k0 += BK) {
#pragma unroll
        for (int i = 0; i < 2; i++) {
            int row = m0 + r + i * 64;
            float4 v = make_float4(0.f, 0.f, 0.f, 0.f);
            if (row < NN)
                v = *(const float4*)(A + (size_t)row * KCH + k0 + kk);
            As[kk + 0][r + i * 64] = v.x;
            As[kk + 1][r + i * 64] = v.y;
            As[kk + 2][r + i * 64] = v.z;
            As[kk + 3][r + i * 64] = v.w;

            int wrow = j0 + r + i * 64;   // always < 256
            float4 u = *(const float4*)(W + (size_t)wrow * KCH + k0 + kk);
            Bs[kk + 0][r + i * 64] = u.x;
            Bs[kk + 1][r + i * 64] = u.y;
            Bs[kk + 2][r + i * 64] = u.z;
            Bs[kk + 3][r + i * 64] = u.w;
        }
        __syncthreads();

#pragma unroll
        for (int k = 0; k < BK; k++) {
            float a[8], b[8];
#pragma unroll
            for (int i = 0; i < 8; i++) a[i] = As[k][ty * 8 + i];
#pragma unroll
            for (int j = 0; j < 8; j++) b[j] = Bs[k][tx * 8 + j];
#pragma unroll
            for (int i = 0; i < 8; i++)
#pragma unroll
                for (int j = 0; j < 8; j++) acc[i][j] += a[i] * b[j];
        }
        __syncthreads();
    }

#pragma unroll
    for (int i = 0; i < 8; i++) {
        int row = m0 + ty * 8 + i;
        if (row < NN) {
            float* cp = g_xp + (size_t)row * KCH + j0 + tx * 8;
            float4 o0 = make_float4(acc[i][0], acc[i][1], acc[i][2], acc[i][3]);
            float4 o1 = make_float4(acc[i][4], acc[i][5], acc[i][6], acc[i][7]);
            *(float4*)(cp)     = o0;
            *(float4*)(cp + 4) = o1;
        }
    }
}

// ---------------- K2: per-node attention logits al/ar --------------------
__global__ void k2_alar(const float* __restrict__ attn_l,
                        const float* __restrict__ attn_r) {
    int idx = blockIdx.x * blockDim.x + threadIdx.x;  // n*8 + h
    if (idx >= NN * HEADS) return;
    int n = idx >> 3, h = idx & 7;
    const float4* xp4 = (const float4*)(g_xp + (size_t)n * KCH + h * OUTC);
    const float4* l4  = (const float4*)(attn_l + h * OUTC);
    const float4* r4  = (const float4*)(attn_r + h * OUTC);
    float sl = 0.f, sr = 0.f;
#pragma unroll
    for (int i = 0; i < 8; i++) {
        float4 v = xp4[i], l = l4[i], rr = r4[i];
        sl += v.x * l.x + v.y * l.y + v.z * l.z + v.w * l.w;
        sr += v.x * rr.x + v.y * rr.y + v.z * rr.z + v.w * rr.w;
    }
    g_al[idx] = sl;
    g_ar[idx] = sr;
}

// ---------------- K3: degree histogram over dst ----------------
__global__ void k3_hist(const void* __restrict__ ei) {
    int e = blockIdx.x * blockDim.x + threadIdx.x;
    if (e >= NE) return;
    int is64 = g_is64;
    int d = ld_idx(ei, NE + e, is64);
    atomicAdd(&g_deg[d], 1);
}

// ---------------- K4: single-block exclusive scan -> rowptr/cursor -------
__global__ void k4_scan() {
    __shared__ int swarp[32];
    __shared__ int stot;
    int tid = threadIdx.x, lane = tid & 31, wid = tid >> 5;
    int carry = 0;
    for (int base = 0; base < NN; base += 1024) {
        int i = base + tid;
        int v = (i < NN) ? g_deg[i] : 0;
        int incl = v;
#pragma unroll
        for (int d = 1; d < 32; d <<= 1) {
            int t = __shfl_up_sync(0xffffffffu, incl, d);
            if (lane >= d) incl += t;
        }
        if (lane == 31) swarp[wid] = incl;
        __syncthreads();
        if (wid == 0) {
            int wv = swarp[lane];
            int wi = wv;
#pragma unroll
            for (int d = 1; d < 32; d <<= 1) {
                int t = __shfl_up_sync(0xffffffffu, wi, d);
                if (lane >= d) wi += t;
            }
            if (lane == 31) stot = wi;
            swarp[lane] = wi - wv;   // exclusive warp offsets
        }
        __syncthreads();
        int excl = carry + swarp[wid] + incl - v;
        if (i < NN) {
            g_rowptr[i] = excl;
            g_cursor[i] = excl;
        }
        carry += stot;
        __syncthreads();
    }
    if (tid == 0) g_rowptr[NN] = carry;
}

// ---------------- K5: scatter edges into CSR buckets ----------------
__global__ void k5_scatter(const void* __restrict__ ei) {
    int e = blockIdx.x * blockDim.x + threadIdx.x;
    if (e >= NE) return;
    int is64 = g_is64;
    int s = ld_idx(ei, e, is64);
    int d = ld_idx(ei, NE + e, is64);
    int pos = atomicAdd(&g_cursor[d], 1);
    g_csrsrc[pos] = s;
}

// ---------------- K6: fused softmax + aggregate (warp per node) ----------
__global__ __launch_bounds__(256) void k6_gather(float* __restrict__ out) {
    int node = blockIdx.x * 8 + (threadIdx.x >> 5);
    if (node >= NN) return;
    int lane = threadIdx.x & 31;
    int c0 = lane * 8;          // 8 channels per lane
    int h  = lane >> 2;         // head index of these channels

    float arn = g_ar[node * HEADS + h];
    float acc0 = 0.f, acc1 = 0.f, acc2 = 0.f, acc3 = 0.f;
    float acc4 = 0.f, acc5 = 0.f, acc6 = 0.f, acc7 = 0.f;
    float wsum = 0.f;

    int start = g_rowptr[node];
    int end   = g_rowptr[node + 1];

    // p == start-1 encodes the self loop (src = node)
    for (int p = start - 1; p < end; p++) {
        int src = (p < start) ? node : g_csrsrc[p];
        float lg = g_al[src * HEADS + h] + arn;
        float a = lg > 0.f ? lg : 0.2f * lg;     // leaky_relu(0.2)
        float w = __expf(a);                     // max-shift cancels in w/wsum
        wsum += w;
        const float4* xv = (const float4*)(g_xp + (size_t)src * KCH + c0);
        float4 v0 = xv[0], v1 = xv[1];
        acc0 += w * v0.x; acc1 += w * v0.y; acc2 += w * v0.z; acc3 += w * v0.w;
        acc4 += w * v1.x; acc5 += w * v1.y; acc6 += w * v1.z; acc7 += w * v1.w;
    }

    float inv = 1.f / fmaxf(wsum, 1e-6f);
    float* op = out + (size_t)node * KCH + c0;
    *(float4*)(op)     = make_float4(acc0 * inv, acc1 * inv, acc2 * inv, acc3 * inv);
    *(float4*)(op + 4) = make_float4(acc4 * inv, acc5 * inv, acc6 * inv, acc7 * inv);
}

// ---------------- launch ----------------
extern "C" void kernel_launch(void* const* d_in, const int* in_sizes, int n_in,
                              void* d_out, int out_size) {
    const float* x      = (const float*)d_in[0];
    const void*  ei     = d_in[1];
    const float* W      = (const float*)d_in[2];
    const float* attn_l = (const float*)d_in[3];
    const float* attn_r = (const float*)d_in[4];
    float*       out    = (float*)d_out;

    kd_detect<<<1, 32>>>(ei);
    k0_zero<<<(NN + 255) / 256, 256>>>();
    dim3 g1(KCH / BN, (NN + BM - 1) / BM);
    k1_gemm<<<g1, 256>>>(x, W);
    k2_alar<<<(NN * HEADS + 255) / 256, 256>>>(attn_l, attn_r);
    k3_hist<<<(NE + 255) / 256, 256>>>(ei);
    k4_scan<<<1, 1024>>>();
    k5_scatter<<<(NE + 255) / 256, 256>>>(ei);
    k6_gather<<<(NN + 7) / 8, 256>>>(out);
}